// round 14
// baseline (speedup 1.0000x reference)
#include <cuda_runtime.h>
#include <cuda_bf16.h>
#include <math.h>
#include <stdint.h>

#define NTOK 8192
#define DIN  768
#define HDIM 256
#define NEXP 8
#define CDIM 64
#define TOUT 512
#define EPSV 2.2204460492503131e-16f

// ---------------- static device scratch (allocation-free rule) ----------------
__device__ int           g_cnt[NEXP];            // zeroed at end of previous launch
__device__ int           g_tok[NEXP * NTOK];
__device__ unsigned char g_slot[NEXP * NTOK];
__device__ float         g_gate[NEXP * NTOK];
__device__ float         g_part[2ull * NTOK * TOUT];

__device__ __nv_bfloat16 g_xhi[NTOK * DIN],        g_xlo[NTOK * DIN];
__device__ __nv_bfloat16 g_w1hi[NEXP * HDIM * DIN], g_w1lo[NEXP * HDIM * DIN];
__device__ __nv_bfloat16 g_w2hi[NEXP * CDIM * HDIM], g_w2lo[NEXP * CDIM * HDIM];
__device__ __nv_bfloat16 g_wmhi[NEXP * TOUT * CDIM], g_wmlo[NEXP * TOUT * CDIM];
__device__ __nv_bfloat16 g_Hhi[(size_t)NEXP * NTOK * HDIM], g_Hlo[(size_t)NEXP * NTOK * HDIM];

// ---------------- helpers ----------------
__device__ __forceinline__ uint32_t smem_u32(const void* p) {
    return (uint32_t)__cvta_generic_to_shared(p);
}
__device__ __forceinline__ void ldmx4(uint32_t* r, uint32_t addr) {
    asm volatile("ldmatrix.sync.aligned.m8n8.x4.shared.b16 {%0,%1,%2,%3}, [%4];\n"
                 : "=r"(r[0]), "=r"(r[1]), "=r"(r[2]), "=r"(r[3]) : "r"(addr));
}
__device__ __forceinline__ void mma16816(float* c, const uint32_t* a, uint32_t b0, uint32_t b1) {
    asm volatile(
        "mma.sync.aligned.m16n8k16.row.col.f32.bf16.bf16.f32 "
        "{%0,%1,%2,%3}, {%4,%5,%6,%7}, {%8,%9}, {%0,%1,%2,%3};\n"
        : "+f"(c[0]), "+f"(c[1]), "+f"(c[2]), "+f"(c[3])
        : "r"(a[0]), "r"(a[1]), "r"(a[2]), "r"(a[3]), "r"(b0), "r"(b1));
}
__device__ __forceinline__ void cp16(uint32_t dst, const void* src) {
    asm volatile("cp.async.cg.shared.global [%0], [%1], 16;" :: "r"(dst), "l"(src));
}
#define CP_COMMIT() asm volatile("cp.async.commit_group;" ::: "memory")
#define CP_WAIT0()  asm volatile("cp.async.wait_group 0;" ::: "memory")

__device__ __forceinline__ void split_store2(__nv_bfloat16* hi, __nv_bfloat16* lo,
                                             size_t off, float v0, float v1) {
    __nv_bfloat16 h0 = __float2bfloat16_rn(v0), h1 = __float2bfloat16_rn(v1);
    __nv_bfloat162 th; th.x = h0; th.y = h1;
    __nv_bfloat162 tl;
    tl.x = __float2bfloat16_rn(v0 - __bfloat162float(h0));
    tl.y = __float2bfloat16_rn(v1 - __bfloat162float(h1));
    *(__nv_bfloat162*)(hi + off) = th;
    *(__nv_bfloat162*)(lo + off) = tl;
}

// ---------------- smem geometry (row pitch 80B, conflict-free ldmatrix) ----------------
#define TSZ(R) ((R) * 80)
#define STG(BM, BN) (2 * TSZ(BM) + 2 * TSZ(BN))
#define SMEM_FC1 (2 * STG(128, 64))    // 61440 -> 3 CTAs/SM
// fused fc2+combine layout:
//   P (phase-1 staging, 2 stages of STG(64,64)) : [0, 40960)
//   O (2 splits x 64 rows x 144B)               : [40960, 59392)
//   B (one Wm subtile: 2 chunks x 2 splits)     : [59392, 100352)
// Phase 2 ping-pongs subtile B buffers between regions B and P.
#define OSM_PITCH 144
#define OSM_PLANE (64 * OSM_PITCH)     // 9216
#define F2C_P_OFF 0
#define F2C_O_OFF 40960
#define F2C_B_OFF 59392
#define F2C_BUFSZ 40960
#define SMEM_F2C  (F2C_B_OFF + F2C_BUFSZ)   // 100352

// ---------------- shared mainloop (cp.async double-buffered, 1 barrier/chunk) ----------------
// Block tile BM x BN x 32K, 8 warps as 2(M) x 4(N); per-warp tile (BM/2) x (BN/4).
// MMA order per accumulator: hh -> hl -> lh (bitwise-stable across tile shapes).
template <int NCH, int BM, int BN>
__device__ __forceinline__ void run_mainloop_cp(
    uint32_t sb,
    const __nv_bfloat16* aghi, const __nv_bfloat16* aglo,
    const __nv_bfloat16* bghi, const __nv_bfloat16* bglo,
    float (&acc)[BM / 32][BN / 32][4])
{
    constexpr int MF = BM / 32;
    constexpr int NF = BN / 32;
    constexpr int AS = TSZ(BM);
    constexpr int BS = TSZ(BN);
    constexpr int ST = STG(BM, BN);
    const int tid  = threadIdx.x;
    const int lane = tid & 31;
    const int wid  = tid >> 5;
    const int warp_m = wid & 1;
    const int warp_n = wid >> 1;

    const uint32_t a_off = (BM == 128) ? ((tid >> 1) * 80 + (tid & 1) * 32)
                                       : ((tid >> 2) * 80 + (tid & 3) * 16);
    const uint32_t b_off = (BN == 128) ? ((tid >> 1) * 80 + (tid & 1) * 32)
                                       : ((tid >> 2) * 80 + (tid & 3) * 16);

    const int ar = warp_m * (BM / 2) + ((lane >> 3) & 1) * 8 + (lane & 7);
    const int ac = (lane >> 4) * 8;
    const uint32_t la = sb + ar * 80 + ac * 2;
    const int br = warp_n * (BN / 4) + ((lane >> 4) << 3) + (lane & 7);
    const int bc = ((lane >> 3) & 1) * 8;
    const uint32_t lb = sb + 2 * AS + br * 80 + bc * 2;

    auto load_stage = [&](int s) {
        const uint32_t st = sb + s * ST;
        if (BM == 128) {
            cp16(st + a_off,           aghi);
            cp16(st + a_off + 16,      aghi + 8);
            cp16(st + AS + a_off,      aglo);
            cp16(st + AS + a_off + 16, aglo + 8);
        } else {
            cp16(st + a_off,      aghi);
            cp16(st + AS + a_off, aglo);
        }
        if (BN == 128) {
            cp16(st + 2 * AS + b_off,           bghi);
            cp16(st + 2 * AS + b_off + 16,      bghi + 8);
            cp16(st + 2 * AS + BS + b_off,      bglo);
            cp16(st + 2 * AS + BS + b_off + 16, bglo + 8);
        } else {
            cp16(st + 2 * AS + b_off,      bghi);
            cp16(st + 2 * AS + BS + b_off, bglo);
        }
        aghi += 32; aglo += 32; bghi += 32; bglo += 32;
    };

    load_stage(0);
    CP_COMMIT();

    for (int ch = 0; ch < NCH; ch++) {
        CP_WAIT0();
        __syncthreads();
        if (ch + 1 < NCH) {
            load_stage((ch + 1) & 1);
            CP_COMMIT();
        }

        const uint32_t sa  = la + (ch & 1) * ST;
        const uint32_t sbb = lb + (ch & 1) * ST;
#pragma unroll
        for (int kk = 0; kk < 2; kk++) {
            uint32_t bh[2 * NF], bl[2 * NF];
            ldmx4(bh, sbb + kk * 32);
            ldmx4(bl, sbb + BS + kk * 32);
            if (NF == 4) {
                ldmx4(bh + 4, sbb + 1280 + kk * 32);
                ldmx4(bl + 4, sbb + BS + 1280 + kk * 32);
            }
#pragma unroll
            for (int mf = 0; mf < MF; mf++) {
                uint32_t ah[4], al[4];
                ldmx4(ah, sa + (uint32_t)(mf * 1280) + kk * 32);
                ldmx4(al, sa + AS + (uint32_t)(mf * 1280) + kk * 32);
#pragma unroll
                for (int nf = 0; nf < NF; nf++)
                    mma16816(acc[mf][nf], ah, bh[2 * nf], bh[2 * nf + 1]);
#pragma unroll
                for (int nf = 0; nf < NF; nf++)
                    mma16816(acc[mf][nf], ah, bl[2 * nf], bl[2 * nf + 1]);
#pragma unroll
                for (int nf = 0; nf < NF; nf++)
                    mma16816(acc[mf][nf], al, bh[2 * nf], bh[2 * nf + 1]);
            }
        }
    }
}

// ---------------- kernel 1: prep = gating + x split ∥ weight split ----------------
__global__ __launch_bounds__(256) void prep_kernel(
    const float* __restrict__ x,  const float* __restrict__ wg,
    const float* __restrict__ W1, const float* __restrict__ W2,
    const float* __restrict__ Wm)
{
    if (blockIdx.x < NTOK / 8) {
        const int tok  = (blockIdx.x * blockDim.x + threadIdx.x) >> 5;
        const int lane = threadIdx.x & 31;
        const float* xr = x + (size_t)tok * DIN;
        __nv_bfloat16* xh = g_xhi + (size_t)tok * DIN;
        __nv_bfloat16* xl = g_xlo + (size_t)tok * DIN;

        float acc[8];
#pragma unroll
        for (int e = 0; e < 8; e++) acc[e] = 0.f;

#pragma unroll
        for (int it = 0; it < DIN / 32; it++) {
            const int d = it * 32 + lane;
            const float xv = xr[d];
            const __nv_bfloat16 h = __float2bfloat16_rn(xv);
            xh[d] = h;
            xl[d] = __float2bfloat16_rn(xv - __bfloat162float(h));
            const float4 w0 = *(const float4*)(wg + d * 8);
            const float4 w1 = *(const float4*)(wg + d * 8 + 4);
            acc[0] += xv * w0.x; acc[1] += xv * w0.y;
            acc[2] += xv * w0.z; acc[3] += xv * w0.w;
            acc[4] += xv * w1.x; acc[5] += xv * w1.y;
            acc[6] += xv * w1.z; acc[7] += xv * w1.w;
        }
#pragma unroll
        for (int e = 0; e < 8; e++)
#pragma unroll
            for (int off = 16; off; off >>= 1)
                acc[e] += __shfl_xor_sync(0xFFFFFFFFu, acc[e], off);

        if (lane == 0) {
            int i0 = 0; float v0 = acc[0];
#pragma unroll
            for (int e = 1; e < 8; e++) if (acc[e] > v0) { v0 = acc[e]; i0 = e; }
            int i1 = -1; float v1 = -3.4e38f;
#pragma unroll
            for (int e = 0; e < 8; e++)
                if (e != i0 && acc[e] > v1) { v1 = acc[e]; i1 = e; }
            const float tt = expf(v1 - v0);
            const float g0 = 1.f / (1.f + tt);
            const float g1 = tt / (1.f + tt);

            int s0 = atomicAdd(&g_cnt[i0], 1);
            g_tok[i0 * NTOK + s0]  = tok;
            g_slot[i0 * NTOK + s0] = 0;
            g_gate[i0 * NTOK + s0] = g0;
            int s1 = atomicAdd(&g_cnt[i1], 1);
            g_tok[i1 * NTOK + s1]  = tok;
            g_slot[i1 * NTOK + s1] = 1;
            g_gate[i1 * NTOK + s1] = g1;
        }
    } else {
        const int stride = 512 * 256;
        const int t = (blockIdx.x - NTOK / 8) * 256 + threadIdx.x;
#define SPLIT_LOOP(SRC, HI, LO, N)                                            \
    for (int i = t; i < (N) / 4; i += stride) {                               \
        const float4 v = ((const float4*)SRC)[i];                             \
        __nv_bfloat162 h01, h23, l01, l23;                                    \
        h01.x = __float2bfloat16_rn(v.x); h01.y = __float2bfloat16_rn(v.y);   \
        h23.x = __float2bfloat16_rn(v.z); h23.y = __float2bfloat16_rn(v.w);   \
        l01.x = __float2bfloat16_rn(v.x - __bfloat162float(h01.x));           \
        l01.y = __float2bfloat16_rn(v.y - __bfloat162float(h01.y));           \
        l23.x = __float2bfloat16_rn(v.z - __bfloat162float(h23.x));           \
        l23.y = __float2bfloat16_rn(v.w - __bfloat162float(h23.y));           \
        ((__nv_bfloat162*)HI)[2 * i]     = h01;                               \
        ((__nv_bfloat162*)HI)[2 * i + 1] = h23;                               \
        ((__nv_bfloat162*)LO)[2 * i]     = l01;                               \
        ((__nv_bfloat162*)LO)[2 * i + 1] = l23;                               \
    }
        SPLIT_LOOP(W1, g_w1hi, g_w1lo, NEXP * HDIM * DIN)
        SPLIT_LOOP(W2, g_w2hi, g_w2lo, NEXP * CDIM * HDIM)
        SPLIT_LOOP(Wm, g_wmhi, g_wmlo, NEXP * TOUT * CDIM)
#undef SPLIT_LOOP
    }
}

// ---------------- kernel 2: fc1 (128x64 tile, cp.async, 3 CTAs/SM) ----------------
__global__ __launch_bounds__(256, 3) void fc1_mma(const float* __restrict__ b1) {
    const int e   = blockIdx.z;
    const int cnt = g_cnt[e];
    const int m0  = blockIdx.x * 128;
    if (m0 >= cnt) return;
    const int n0  = blockIdx.y * 64;
    const int tid = threadIdx.x;

    extern __shared__ char dsm[];
    const uint32_t sb = smem_u32(dsm);

    const int arow = tid >> 1;
    int r = m0 + arow; if (r >= cnt) r = cnt - 1;
    const int tok = g_tok[e * NTOK + r];
    const __nv_bfloat16* aghi = g_xhi + (size_t)tok * DIN + (tid & 1) * 16;
    const __nv_bfloat16* aglo = g_xlo + (size_t)tok * DIN + (tid & 1) * 16;
    const int brow = tid >> 2;
    const __nv_bfloat16* bghi = g_w1hi + ((size_t)e * HDIM + n0 + brow) * DIN + (tid & 3) * 8;
    const __nv_bfloat16* bglo = g_w1lo + ((size_t)e * HDIM + n0 + brow) * DIN + (tid & 3) * 8;

    float acc[4][2][4] = {};
    run_mainloop_cp<DIN / 32, 128, 64>(sb, aghi, aglo, bghi, bglo, acc);

    const int lane = tid & 31, wid = tid >> 5;
    const int warp_m = wid & 1, warp_n = wid >> 1;
#pragma unroll
    for (int nf = 0; nf < 2; nf++) {
        const int n = n0 + warp_n * 16 + nf * 8 + 2 * (lane & 3);
        const float bb0 = b1[e * HDIM + n];
        const float bb1 = b1[e * HDIM + n + 1];
#pragma unroll
        for (int mf = 0; mf < 4; mf++)
#pragma unroll
            for (int hr = 0; hr < 2; hr++) {
                const int m = m0 + warp_m * 64 + mf * 16 + (lane >> 2) + hr * 8;
                if (m < cnt) {
                    const float h0 = fmaxf(acc[mf][nf][2 * hr + 0] + bb0, 0.f);
                    const float h1 = fmaxf(acc[mf][nf][2 * hr + 1] + bb1, 0.f);
                    split_store2(g_Hhi, g_Hlo, ((size_t)e * NTOK + m) * HDIM + n, h0, h1);
                }
            }
    }
}

// ---------------- kernel 3: fused fc2 + combine (pipelined Wm prefetch) ----------------
// Phase 1: fc2 64x64x256 tile -> gate-scaled O split hi/lo into smem region O.
// Phase 2: 4 Wm subtiles (BN=128, K=64); B buffers ping-pong between regions B and P,
//          prefetched one subtile ahead (subtile 0 prefetched at kernel entry).
__global__ __launch_bounds__(256, 2) void fc2cmb_mma(const float* __restrict__ b2) {
    const int e   = blockIdx.z;
    const int cnt = g_cnt[e];
    const int m0  = blockIdx.x * 64;
    if (m0 >= cnt) return;
    const int tid = threadIdx.x, lane = tid & 31, wid = tid >> 5;
    const int warp_m = wid & 1, warp_n = wid >> 1;

    extern __shared__ char dsm[];
    const uint32_t sb = smem_u32(dsm);

    // ---- Wm producer mapping (per-thread) ----
    const int brow2 = tid >> 1, bhf = tid & 1;
    const __nv_bfloat16* wmh = g_wmhi + ((size_t)e * TOUT + brow2) * CDIM + bhf * 16;
    const __nv_bfloat16* wml = g_wmlo + ((size_t)e * TOUT + brow2) * CDIM + bhf * 16;
    const uint32_t bo = (uint32_t)(brow2 * 80 + bhf * 32);

    auto load_wm = [&](int s, uint32_t buf) {
        const int n0 = s * 128;
#pragma unroll
        for (int c = 0; c < 2; c++) {
            const __nv_bfloat16* sh = wmh + (size_t)n0 * CDIM + c * 32;
            const __nv_bfloat16* sl = wml + (size_t)n0 * CDIM + c * 32;
            const uint32_t dst = buf + c * 20480;
            cp16(dst + bo,              sh);
            cp16(dst + bo + 16,         sh + 8);
            cp16(dst + 10240 + bo,      sl);
            cp16(dst + 10240 + bo + 16, sl + 8);
        }
    };

    // prefetch subtile 0 into region B — independent of phase 1, hides its load
    load_wm(0, sb + F2C_B_OFF);
    CP_COMMIT();

    // ---- phase 1: fc2 mainloop (identical math/order) ----
    {
        const int arow = tid >> 2;
        const __nv_bfloat16* aghi = g_Hhi + ((size_t)e * NTOK + m0 + arow) * HDIM + (tid & 3) * 8;
        const __nv_bfloat16* aglo = g_Hlo + ((size_t)e * NTOK + m0 + arow) * HDIM + (tid & 3) * 8;
        const int brow = tid >> 2;
        const __nv_bfloat16* bghi = g_w2hi + ((size_t)e * CDIM + brow) * HDIM + (tid & 3) * 8;
        const __nv_bfloat16* bglo = g_w2lo + ((size_t)e * CDIM + brow) * HDIM + (tid & 3) * 8;

        float acc1[2][2][4] = {};
        run_mainloop_cp<HDIM / 32, 64, 64>(sb, aghi, aglo, bghi, bglo, acc1);

        // epilogue: O = (acc + b2) * gate, split hi/lo -> region O (pitch 144)
#pragma unroll
        for (int nf = 0; nf < 2; nf++) {
            const int n = warp_n * 16 + nf * 8 + 2 * (lane & 3);
            const float bb0 = b2[e * CDIM + n];
            const float bb1 = b2[e * CDIM + n + 1];
#pragma unroll
            for (int mf = 0; mf < 2; mf++)
#pragma unroll
                for (int hr = 0; hr < 2; hr++) {
                    const int ml = warp_m * 32 + mf * 16 + (lane >> 2) + hr * 8;
                    const int m  = m0 + ml;
                    const float g = (m < cnt) ? g_gate[e * NTOK + m] : 0.f;
                    const float o0 = (acc1[mf][nf][2 * hr + 0] + bb0) * g;
                    const float o1 = (acc1[mf][nf][2 * hr + 1] + bb1) * g;
                    __nv_bfloat16 h0 = __float2bfloat16_rn(o0), h1 = __float2bfloat16_rn(o1);
                    __nv_bfloat162 th; th.x = h0; th.y = h1;
                    __nv_bfloat162 tl;
                    tl.x = __float2bfloat16_rn(o0 - __bfloat162float(h0));
                    tl.y = __float2bfloat16_rn(o1 - __bfloat162float(h1));
                    *(__nv_bfloat162*)(dsm + F2C_O_OFF + ml * OSM_PITCH + n * 2) = th;
                    *(__nv_bfloat162*)(dsm + F2C_O_OFF + OSM_PLANE + ml * OSM_PITCH + n * 2) = tl;
                }
        }
    }

    // ---- phase 2 ----
    const int ar2 = warp_m * 32 + ((lane >> 3) & 1) * 8 + (lane & 7);
    const uint32_t la2 = sb + F2C_O_OFF + ar2 * OSM_PITCH + ((lane >> 4) * 8) * 2;
    const int br2 = warp_n * 32 + ((lane >> 4) << 3) + (lane & 7);
    const uint32_t lbo2 = (uint32_t)(br2 * 80 + (((lane >> 3) & 1) * 8) * 2);

    // row bookkeeping
    int mrow[2][2], tokr[2][2], slotr[2][2];
#pragma unroll
    for (int mf = 0; mf < 2; mf++)
#pragma unroll
        for (int hr = 0; hr < 2; hr++) {
            const int m = m0 + warp_m * 32 + mf * 16 + (lane >> 2) + hr * 8;
            mrow[mf][hr] = m;
            tokr[mf][hr] = (m < cnt) ? g_tok[e * NTOK + m] : 0;
            slotr[mf][hr] = (m < cnt) ? g_slot[e * NTOK + m] : 0;
        }

    for (int s = 0; s < 4; s++) {
        const uint32_t buf = sb + ((s & 1) ? F2C_P_OFF : F2C_B_OFF);
        CP_WAIT0();
        __syncthreads();   // buf[s] ready; all warps done with buf[s-2]'s region
        if (s + 1 < 4) {
            load_wm(s + 1, sb + (((s + 1) & 1) ? F2C_P_OFF : F2C_B_OFF));
            CP_COMMIT();
        }

        const int n0 = s * 128;
        float acc2[2][4][4] = {};
#pragma unroll
        for (int ch = 0; ch < 2; ch++) {
#pragma unroll
            for (int kk = 0; kk < 2; kk++) {
                uint32_t bh[8], bl[8];
                ldmx4(bh,     buf + lbo2 + ch * 20480 + kk * 32);
                ldmx4(bh + 4, buf + lbo2 + ch * 20480 + 1280 + kk * 32);
                ldmx4(bl,     buf + lbo2 + ch * 20480 + 10240 + kk * 32);
                ldmx4(bl + 4, buf + lbo2 + ch * 20480 + 10240 + 1280 + kk * 32);
#pragma unroll
                for (int mf = 0; mf < 2; mf++) {
                    uint32_t ah[4], al[4];
                    ldmx4(ah, la2 + (uint32_t)(mf * 16 * OSM_PITCH) + ch * 64 + kk * 32);
                    ldmx4(al, la2 + OSM_PLANE + (uint32_t)(mf * 16 * OSM_PITCH) + ch * 64 + kk * 32);
#pragma unroll
                    for (int nf = 0; nf < 4; nf++)
                        mma16816(acc2[mf][nf], ah, bh[2 * nf], bh[2 * nf + 1]);
#pragma unroll
                    for (int nf = 0; nf < 4; nf++)
                        mma16816(acc2[mf][nf], ah, bl[2 * nf], bl[2 * nf + 1]);
#pragma unroll
                    for (int nf = 0; nf < 4; nf++)
                        mma16816(acc2[mf][nf], al, bh[2 * nf], bh[2 * nf + 1]);
                }
            }
        }

        // epilogue: partial stores (same mapping/values as before)
#pragma unroll
        for (int mf = 0; mf < 2; mf++)
#pragma unroll
            for (int hr = 0; hr < 2; hr++) {
                if (mrow[mf][hr] < cnt) {
                    float* yr = g_part + ((size_t)slotr[mf][hr] * NTOK + tokr[mf][hr]) * TOUT + n0;
#pragma unroll
                    for (int nf = 0; nf < 4; nf++) {
                        const int n = warp_n * 32 + nf * 8 + 2 * (lane & 3);
                        float2 v;
                        v.x = acc2[mf][nf][2 * hr + 0];
                        v.y = acc2[mf][nf][2 * hr + 1];
                        *(float2*)(yr + n) = v;
                    }
                }
            }
    }
}

// ---------------- kernel 5: finish — y = p0 + p1, EPS fixup; reset g_cnt ----------------
__global__ void finish_kernel(float4* __restrict__ y) {
    if (blockIdx.x == 0 && threadIdx.x < NEXP) g_cnt[threadIdx.x] = 0;  // clean for next launch
    const int n = NTOK * TOUT / 4;
    const float4* p0 = (const float4*)g_part;
    const float4* p1 = (const float4*)(g_part + (size_t)NTOK * TOUT);
    for (int i = blockIdx.x * blockDim.x + threadIdx.x; i < n;
         i += gridDim.x * blockDim.x) {
        const float4 a = p0[i];
        const float4 b = p1[i];
        float4 v;
        v.x = a.x + b.x; v.y = a.y + b.y; v.z = a.z + b.z; v.w = a.w + b.w;
        if (v.x == 0.f) v.x = EPSV;
        if (v.y == 0.f) v.y = EPSV;
        if (v.z == 0.f) v.z = EPSV;
        if (v.w == 0.f) v.w = EPSV;
        y[i] = v;
    }
}

// ---------------- launch ----------------
extern "C" void kernel_launch(void* const* d_in, const int* in_sizes, int n_in,
                              void* d_out, int out_size) {
    const float* x  = (const float*)d_in[0];
    // d_in[1] = labels (int64) — unused by the reference computation
    const float* wg = (const float*)d_in[2];
    const float* W1 = (const float*)d_in[3];
    const float* b1 = (const float*)d_in[4];
    const float* W2 = (const float*)d_in[5];
    const float* b2 = (const float*)d_in[6];
    const float* Wm = (const float*)d_in[7];
    float* y = (float*)d_out;

    cudaFuncSetAttribute(fc1_mma,    cudaFuncAttributeMaxDynamicSharedMemorySize, SMEM_FC1);
    cudaFuncSetAttribute(fc2cmb_mma, cudaFuncAttributeMaxDynamicSharedMemorySize, SMEM_F2C);

    prep_kernel<<<NTOK / 8 + 512, 256>>>(x, wg, W1, W2, Wm);

    dim3 g1(NTOK / 128, HDIM / 64, NEXP);   // (64, 4, 8)
    fc1_mma<<<g1, 256, SMEM_FC1>>>(b1);

    dim3 g2(NTOK / 64, 1, NEXP);            // (128, 1, 8)
    fc2cmb_mma<<<g2, 256, SMEM_F2C>>>(b2);

    finish_kernel<<<1024, 256>>>((float4*)y);
}

// round 17
// speedup vs baseline: 1.0696x; 1.0696x over previous
#include <cuda_runtime.h>
#include <cuda_bf16.h>
#include <math.h>
#include <stdint.h>

#define NTOK 8192
#define DIN  768
#define HDIM 256
#define NEXP 8
#define CDIM 64
#define TOUT 512
#define EPSV 2.2204460492503131e-16f

// ---------------- static device scratch (allocation-free rule) ----------------
__device__ int           g_cnt[NEXP];            // zeroed at end of previous launch
__device__ int           g_tok[NEXP * NTOK];
__device__ unsigned char g_slot[NEXP * NTOK];
__device__ float         g_gate[NEXP * NTOK];
__device__ float         g_part[2ull * NTOK * TOUT];

__device__ __nv_bfloat16 g_xhi[NTOK * DIN],        g_xlo[NTOK * DIN];
__device__ __nv_bfloat16 g_w1hi[NEXP * HDIM * DIN], g_w1lo[NEXP * HDIM * DIN];
__device__ __nv_bfloat16 g_w2hi[NEXP * CDIM * HDIM], g_w2lo[NEXP * CDIM * HDIM];
__device__ __nv_bfloat16 g_wmhi[NEXP * TOUT * CDIM], g_wmlo[NEXP * TOUT * CDIM];
__device__ __nv_bfloat16 g_Hhi[(size_t)NEXP * NTOK * HDIM], g_Hlo[(size_t)NEXP * NTOK * HDIM];

// ---------------- helpers ----------------
__device__ __forceinline__ uint32_t smem_u32(const void* p) {
    return (uint32_t)__cvta_generic_to_shared(p);
}
__device__ __forceinline__ void ldmx4(uint32_t* r, uint32_t addr) {
    asm volatile("ldmatrix.sync.aligned.m8n8.x4.shared.b16 {%0,%1,%2,%3}, [%4];\n"
                 : "=r"(r[0]), "=r"(r[1]), "=r"(r[2]), "=r"(r[3]) : "r"(addr));
}
__device__ __forceinline__ void mma16816(float* c, const uint32_t* a, uint32_t b0, uint32_t b1) {
    asm volatile(
        "mma.sync.aligned.m16n8k16.row.col.f32.bf16.bf16.f32 "
        "{%0,%1,%2,%3}, {%4,%5,%6,%7}, {%8,%9}, {%0,%1,%2,%3};\n"
        : "+f"(c[0]), "+f"(c[1]), "+f"(c[2]), "+f"(c[3])
        : "r"(a[0]), "r"(a[1]), "r"(a[2]), "r"(a[3]), "r"(b0), "r"(b1));
}
__device__ __forceinline__ void cp16(uint32_t dst, const void* src) {
    asm volatile("cp.async.cg.shared.global [%0], [%1], 16;" :: "r"(dst), "l"(src));
}
#define CP_COMMIT() asm volatile("cp.async.commit_group;" ::: "memory")
#define CP_WAIT0()  asm volatile("cp.async.wait_group 0;" ::: "memory")

__device__ __forceinline__ void split_store2(__nv_bfloat16* hi, __nv_bfloat16* lo,
                                             size_t off, float v0, float v1) {
    __nv_bfloat16 h0 = __float2bfloat16_rn(v0), h1 = __float2bfloat16_rn(v1);
    __nv_bfloat162 th; th.x = h0; th.y = h1;
    __nv_bfloat162 tl;
    tl.x = __float2bfloat16_rn(v0 - __bfloat162float(h0));
    tl.y = __float2bfloat16_rn(v1 - __bfloat162float(h1));
    *(__nv_bfloat162*)(hi + off) = th;
    *(__nv_bfloat162*)(lo + off) = tl;
}

// ---------------- smem geometry (row pitch 80B, conflict-free ldmatrix) ----------------
#define TSZ(R) ((R) * 80)
#define STG(BM, BN) (2 * TSZ(BM) + 2 * TSZ(BN))
#define SMEM_FC1 (2 * STG(128, 128))   // 81920 -> 2 CTAs/SM (best measured config)
// fused fc2+combine layout:
//   P (phase-1 staging, 2 stages of STG(64,64)) : [0, 40960)
//   O (2 splits x 64 rows x 144B)               : [40960, 59392)
//   B (one Wm subtile: 2 chunks x 2 splits)     : [59392, 100352)
// Phase 2 ping-pongs subtile B buffers between regions B and P.
#define OSM_PITCH 144
#define OSM_PLANE (64 * OSM_PITCH)     // 9216
#define F2C_P_OFF 0
#define F2C_O_OFF 40960
#define F2C_B_OFF 59392
#define F2C_BUFSZ 40960
#define SMEM_F2C  (F2C_B_OFF + F2C_BUFSZ)   // 100352

// ---------------- shared mainloop (cp.async double-buffered, 1 barrier/chunk) ----------------
// Block tile BM x BN x 32K, 8 warps as 2(M) x 4(N); per-warp tile (BM/2) x (BN/4).
// MMA order per accumulator: hh -> hl -> lh (bitwise-stable across tile shapes).
template <int NCH, int BM, int BN>
__device__ __forceinline__ void run_mainloop_cp(
    uint32_t sb,
    const __nv_bfloat16* aghi, const __nv_bfloat16* aglo,
    const __nv_bfloat16* bghi, const __nv_bfloat16* bglo,
    float (&acc)[BM / 32][BN / 32][4])
{
    constexpr int MF = BM / 32;
    constexpr int NF = BN / 32;
    constexpr int AS = TSZ(BM);
    constexpr int BS = TSZ(BN);
    constexpr int ST = STG(BM, BN);
    const int tid  = threadIdx.x;
    const int lane = tid & 31;
    const int wid  = tid >> 5;
    const int warp_m = wid & 1;
    const int warp_n = wid >> 1;

    const uint32_t a_off = (BM == 128) ? ((tid >> 1) * 80 + (tid & 1) * 32)
                                       : ((tid >> 2) * 80 + (tid & 3) * 16);
    const uint32_t b_off = (BN == 128) ? ((tid >> 1) * 80 + (tid & 1) * 32)
                                       : ((tid >> 2) * 80 + (tid & 3) * 16);

    const int ar = warp_m * (BM / 2) + ((lane >> 3) & 1) * 8 + (lane & 7);
    const int ac = (lane >> 4) * 8;
    const uint32_t la = sb + ar * 80 + ac * 2;
    const int br = warp_n * (BN / 4) + ((lane >> 4) << 3) + (lane & 7);
    const int bc = ((lane >> 3) & 1) * 8;
    const uint32_t lb = sb + 2 * AS + br * 80 + bc * 2;

    auto load_stage = [&](int s) {
        const uint32_t st = sb + s * ST;
        if (BM == 128) {
            cp16(st + a_off,           aghi);
            cp16(st + a_off + 16,      aghi + 8);
            cp16(st + AS + a_off,      aglo);
            cp16(st + AS + a_off + 16, aglo + 8);
        } else {
            cp16(st + a_off,      aghi);
            cp16(st + AS + a_off, aglo);
        }
        if (BN == 128) {
            cp16(st + 2 * AS + b_off,           bghi);
            cp16(st + 2 * AS + b_off + 16,      bghi + 8);
            cp16(st + 2 * AS + BS + b_off,      bglo);
            cp16(st + 2 * AS + BS + b_off + 16, bglo + 8);
        } else {
            cp16(st + 2 * AS + b_off,      bghi);
            cp16(st + 2 * AS + BS + b_off, bglo);
        }
        aghi += 32; aglo += 32; bghi += 32; bglo += 32;
    };

    load_stage(0);
    CP_COMMIT();

    for (int ch = 0; ch < NCH; ch++) {
        CP_WAIT0();
        __syncthreads();
        if (ch + 1 < NCH) {
            load_stage((ch + 1) & 1);
            CP_COMMIT();
        }

        const uint32_t sa  = la + (ch & 1) * ST;
        const uint32_t sbb = lb + (ch & 1) * ST;
#pragma unroll
        for (int kk = 0; kk < 2; kk++) {
            uint32_t bh[2 * NF], bl[2 * NF];
            ldmx4(bh, sbb + kk * 32);
            ldmx4(bl, sbb + BS + kk * 32);
            if (NF == 4) {
                ldmx4(bh + 4, sbb + 1280 + kk * 32);
                ldmx4(bl + 4, sbb + BS + 1280 + kk * 32);
            }
#pragma unroll
            for (int mf = 0; mf < MF; mf++) {
                uint32_t ah[4], al[4];
                ldmx4(ah, sa + (uint32_t)(mf * 1280) + kk * 32);
                ldmx4(al, sa + AS + (uint32_t)(mf * 1280) + kk * 32);
#pragma unroll
                for (int nf = 0; nf < NF; nf++)
                    mma16816(acc[mf][nf], ah, bh[2 * nf], bh[2 * nf + 1]);
#pragma unroll
                for (int nf = 0; nf < NF; nf++)
                    mma16816(acc[mf][nf], ah, bl[2 * nf], bl[2 * nf + 1]);
#pragma unroll
                for (int nf = 0; nf < NF; nf++)
                    mma16816(acc[mf][nf], al, bh[2 * nf], bh[2 * nf + 1]);
            }
        }
    }
}

// ---------------- kernel 1: prep = gating + x split ∥ weight split ----------------
__global__ __launch_bounds__(256) void prep_kernel(
    const float* __restrict__ x,  const float* __restrict__ wg,
    const float* __restrict__ W1, const float* __restrict__ W2,
    const float* __restrict__ Wm)
{
    if (blockIdx.x < NTOK / 8) {
        const int tok  = (blockIdx.x * blockDim.x + threadIdx.x) >> 5;
        const int lane = threadIdx.x & 31;
        const float* xr = x + (size_t)tok * DIN;
        __nv_bfloat16* xh = g_xhi + (size_t)tok * DIN;
        __nv_bfloat16* xl = g_xlo + (size_t)tok * DIN;

        float acc[8];
#pragma unroll
        for (int e = 0; e < 8; e++) acc[e] = 0.f;

#pragma unroll
        for (int it = 0; it < DIN / 32; it++) {
            const int d = it * 32 + lane;
            const float xv = xr[d];
            const __nv_bfloat16 h = __float2bfloat16_rn(xv);
            xh[d] = h;
            xl[d] = __float2bfloat16_rn(xv - __bfloat162float(h));
            const float4 w0 = *(const float4*)(wg + d * 8);
            const float4 w1 = *(const float4*)(wg + d * 8 + 4);
            acc[0] += xv * w0.x; acc[1] += xv * w0.y;
            acc[2] += xv * w0.z; acc[3] += xv * w0.w;
            acc[4] += xv * w1.x; acc[5] += xv * w1.y;
            acc[6] += xv * w1.z; acc[7] += xv * w1.w;
        }
#pragma unroll
        for (int e = 0; e < 8; e++)
#pragma unroll
            for (int off = 16; off; off >>= 1)
                acc[e] += __shfl_xor_sync(0xFFFFFFFFu, acc[e], off);

        if (lane == 0) {
            int i0 = 0; float v0 = acc[0];
#pragma unroll
            for (int e = 1; e < 8; e++) if (acc[e] > v0) { v0 = acc[e]; i0 = e; }
            int i1 = -1; float v1 = -3.4e38f;
#pragma unroll
            for (int e = 0; e < 8; e++)
                if (e != i0 && acc[e] > v1) { v1 = acc[e]; i1 = e; }
            const float tt = expf(v1 - v0);
            const float g0 = 1.f / (1.f + tt);
            const float g1 = tt / (1.f + tt);

            int s0 = atomicAdd(&g_cnt[i0], 1);
            g_tok[i0 * NTOK + s0]  = tok;
            g_slot[i0 * NTOK + s0] = 0;
            g_gate[i0 * NTOK + s0] = g0;
            int s1 = atomicAdd(&g_cnt[i1], 1);
            g_tok[i1 * NTOK + s1]  = tok;
            g_slot[i1 * NTOK + s1] = 1;
            g_gate[i1 * NTOK + s1] = g1;
        }
    } else {
        const int stride = 512 * 256;
        const int t = (blockIdx.x - NTOK / 8) * 256 + threadIdx.x;
#define SPLIT_LOOP(SRC, HI, LO, N)                                            \
    for (int i = t; i < (N) / 4; i += stride) {                               \
        const float4 v = ((const float4*)SRC)[i];                             \
        __nv_bfloat162 h01, h23, l01, l23;                                    \
        h01.x = __float2bfloat16_rn(v.x); h01.y = __float2bfloat16_rn(v.y);   \
        h23.x = __float2bfloat16_rn(v.z); h23.y = __float2bfloat16_rn(v.w);   \
        l01.x = __float2bfloat16_rn(v.x - __bfloat162float(h01.x));           \
        l01.y = __float2bfloat16_rn(v.y - __bfloat162float(h01.y));           \
        l23.x = __float2bfloat16_rn(v.z - __bfloat162float(h23.x));           \
        l23.y = __float2bfloat16_rn(v.w - __bfloat162float(h23.y));           \
        ((__nv_bfloat162*)HI)[2 * i]     = h01;                               \
        ((__nv_bfloat162*)HI)[2 * i + 1] = h23;                               \
        ((__nv_bfloat162*)LO)[2 * i]     = l01;                               \
        ((__nv_bfloat162*)LO)[2 * i + 1] = l23;                               \
    }
        SPLIT_LOOP(W1, g_w1hi, g_w1lo, NEXP * HDIM * DIN)
        SPLIT_LOOP(W2, g_w2hi, g_w2lo, NEXP * CDIM * HDIM)
        SPLIT_LOOP(Wm, g_wmhi, g_wmlo, NEXP * TOUT * CDIM)
#undef SPLIT_LOOP
    }
}

// ---------------- kernel 2: fc1 (128x128 tile, cp.async, 2 CTAs/SM) ----------------
__global__ __launch_bounds__(256, 2) void fc1_mma(const float* __restrict__ b1) {
    const int e   = blockIdx.z;
    const int cnt = g_cnt[e];
    const int m0  = blockIdx.x * 128;
    if (m0 >= cnt) return;
    const int n0  = blockIdx.y * 128;
    const int tid = threadIdx.x;

    extern __shared__ char dsm[];
    const uint32_t sb = smem_u32(dsm);

    const int arow = tid >> 1;
    int r = m0 + arow; if (r >= cnt) r = cnt - 1;
    const int tok = g_tok[e * NTOK + r];
    const __nv_bfloat16* aghi = g_xhi + (size_t)tok * DIN + (tid & 1) * 16;
    const __nv_bfloat16* aglo = g_xlo + (size_t)tok * DIN + (tid & 1) * 16;
    const int brow = tid >> 1;
    const __nv_bfloat16* bghi = g_w1hi + ((size_t)e * HDIM + n0 + brow) * DIN + (tid & 1) * 16;
    const __nv_bfloat16* bglo = g_w1lo + ((size_t)e * HDIM + n0 + brow) * DIN + (tid & 1) * 16;

    float acc[4][4][4] = {};
    run_mainloop_cp<DIN / 32, 128, 128>(sb, aghi, aglo, bghi, bglo, acc);

    const int lane = tid & 31, wid = tid >> 5;
    const int warp_m = wid & 1, warp_n = wid >> 1;
#pragma unroll
    for (int nf = 0; nf < 4; nf++) {
        const int n = n0 + warp_n * 32 + nf * 8 + 2 * (lane & 3);
        const float bb0 = b1[e * HDIM + n];
        const float bb1 = b1[e * HDIM + n + 1];
#pragma unroll
        for (int mf = 0; mf < 4; mf++)
#pragma unroll
            for (int hr = 0; hr < 2; hr++) {
                const int m = m0 + warp_m * 64 + mf * 16 + (lane >> 2) + hr * 8;
                if (m < cnt) {
                    const float h0 = fmaxf(acc[mf][nf][2 * hr + 0] + bb0, 0.f);
                    const float h1 = fmaxf(acc[mf][nf][2 * hr + 1] + bb1, 0.f);
                    split_store2(g_Hhi, g_Hlo, ((size_t)e * NTOK + m) * HDIM + n, h0, h1);
                }
            }
    }
}

// ---------------- kernel 3: fused fc2 + combine (pipelined Wm prefetch) ----------------
// Phase 1: fc2 64x64x256 tile -> gate-scaled O split hi/lo into smem region O.
// Phase 2: 4 Wm subtiles (BN=128, K=64); B buffers ping-pong between regions B and P,
//          prefetched one subtile ahead (subtile 0 prefetched at kernel entry).
__global__ __launch_bounds__(256, 2) void fc2cmb_mma(const float* __restrict__ b2) {
    const int e   = blockIdx.z;
    const int cnt = g_cnt[e];
    const int m0  = blockIdx.x * 64;
    if (m0 >= cnt) return;
    const int tid = threadIdx.x, lane = tid & 31, wid = tid >> 5;
    const int warp_m = wid & 1, warp_n = wid >> 1;

    extern __shared__ char dsm[];
    const uint32_t sb = smem_u32(dsm);

    // ---- Wm producer mapping (per-thread) ----
    const int brow2 = tid >> 1, bhf = tid & 1;
    const __nv_bfloat16* wmh = g_wmhi + ((size_t)e * TOUT + brow2) * CDIM + bhf * 16;
    const __nv_bfloat16* wml = g_wmlo + ((size_t)e * TOUT + brow2) * CDIM + bhf * 16;
    const uint32_t bo = (uint32_t)(brow2 * 80 + bhf * 32);

    auto load_wm = [&](int s, uint32_t buf) {
        const int n0 = s * 128;
#pragma unroll
        for (int c = 0; c < 2; c++) {
            const __nv_bfloat16* sh = wmh + (size_t)n0 * CDIM + c * 32;
            const __nv_bfloat16* sl = wml + (size_t)n0 * CDIM + c * 32;
            const uint32_t dst = buf + c * 20480;
            cp16(dst + bo,              sh);
            cp16(dst + bo + 16,         sh + 8);
            cp16(dst + 10240 + bo,      sl);
            cp16(dst + 10240 + bo + 16, sl + 8);
        }
    };

    // prefetch subtile 0 into region B — independent of phase 1, hides its load
    load_wm(0, sb + F2C_B_OFF);
    CP_COMMIT();

    // ---- phase 1: fc2 mainloop (identical math/order) ----
    {
        const int arow = tid >> 2;
        const __nv_bfloat16* aghi = g_Hhi + ((size_t)e * NTOK + m0 + arow) * HDIM + (tid & 3) * 8;
        const __nv_bfloat16* aglo = g_Hlo + ((size_t)e * NTOK + m0 + arow) * HDIM + (tid & 3) * 8;
        const int brow = tid >> 2;
        const __nv_bfloat16* bghi = g_w2hi + ((size_t)e * CDIM + brow) * HDIM + (tid & 3) * 8;
        const __nv_bfloat16* bglo = g_w2lo + ((size_t)e * CDIM + brow) * HDIM + (tid & 3) * 8;

        float acc1[2][2][4] = {};
        run_mainloop_cp<HDIM / 32, 64, 64>(sb, aghi, aglo, bghi, bglo, acc1);

        // epilogue: O = (acc + b2) * gate, split hi/lo -> region O (pitch 144)
#pragma unroll
        for (int nf = 0; nf < 2; nf++) {
            const int n = warp_n * 16 + nf * 8 + 2 * (lane & 3);
            const float bb0 = b2[e * CDIM + n];
            const float bb1 = b2[e * CDIM + n + 1];
#pragma unroll
            for (int mf = 0; mf < 2; mf++)
#pragma unroll
                for (int hr = 0; hr < 2; hr++) {
                    const int ml = warp_m * 32 + mf * 16 + (lane >> 2) + hr * 8;
                    const int m  = m0 + ml;
                    const float g = (m < cnt) ? g_gate[e * NTOK + m] : 0.f;
                    const float o0 = (acc1[mf][nf][2 * hr + 0] + bb0) * g;
                    const float o1 = (acc1[mf][nf][2 * hr + 1] + bb1) * g;
                    __nv_bfloat16 h0 = __float2bfloat16_rn(o0), h1 = __float2bfloat16_rn(o1);
                    __nv_bfloat162 th; th.x = h0; th.y = h1;
                    __nv_bfloat162 tl;
                    tl.x = __float2bfloat16_rn(o0 - __bfloat162float(h0));
                    tl.y = __float2bfloat16_rn(o1 - __bfloat162float(h1));
                    *(__nv_bfloat162*)(dsm + F2C_O_OFF + ml * OSM_PITCH + n * 2) = th;
                    *(__nv_bfloat162*)(dsm + F2C_O_OFF + OSM_PLANE + ml * OSM_PITCH + n * 2) = tl;
                }
        }
    }

    // ---- phase 2 ----
    const int ar2 = warp_m * 32 + ((lane >> 3) & 1) * 8 + (lane & 7);
    const uint32_t la2 = sb + F2C_O_OFF + ar2 * OSM_PITCH + ((lane >> 4) * 8) * 2;
    const int br2 = warp_n * 32 + ((lane >> 4) << 3) + (lane & 7);
    const uint32_t lbo2 = (uint32_t)(br2 * 80 + (((lane >> 3) & 1) * 8) * 2);

    // row bookkeeping
    int mrow[2][2], tokr[2][2], slotr[2][2];
#pragma unroll
    for (int mf = 0; mf < 2; mf++)
#pragma unroll
        for (int hr = 0; hr < 2; hr++) {
            const int m = m0 + warp_m * 32 + mf * 16 + (lane >> 2) + hr * 8;
            mrow[mf][hr] = m;
            tokr[mf][hr] = (m < cnt) ? g_tok[e * NTOK + m] : 0;
            slotr[mf][hr] = (m < cnt) ? g_slot[e * NTOK + m] : 0;
        }

    for (int s = 0; s < 4; s++) {
        const uint32_t buf = sb + ((s & 1) ? F2C_P_OFF : F2C_B_OFF);
        CP_WAIT0();
        __syncthreads();   // buf[s] ready; all warps done with buf[s-2]'s region
        if (s + 1 < 4) {
            load_wm(s + 1, sb + (((s + 1) & 1) ? F2C_P_OFF : F2C_B_OFF));
            CP_COMMIT();
        }

        const int n0 = s * 128;
        float acc2[2][4][4] = {};
#pragma unroll
        for (int ch = 0; ch < 2; ch++) {
#pragma unroll
            for (int kk = 0; kk < 2; kk++) {
                uint32_t bh[8], bl[8];
                ldmx4(bh,     buf + lbo2 + ch * 20480 + kk * 32);
                ldmx4(bh + 4, buf + lbo2 + ch * 20480 + 1280 + kk * 32);
                ldmx4(bl,     buf + lbo2 + ch * 20480 + 10240 + kk * 32);
                ldmx4(bl + 4, buf + lbo2 + ch * 20480 + 10240 + 1280 + kk * 32);
#pragma unroll
                for (int mf = 0; mf < 2; mf++) {
                    uint32_t ah[4], al[4];
                    ldmx4(ah, la2 + (uint32_t)(mf * 16 * OSM_PITCH) + ch * 64 + kk * 32);
                    ldmx4(al, la2 + OSM_PLANE + (uint32_t)(mf * 16 * OSM_PITCH) + ch * 64 + kk * 32);
#pragma unroll
                    for (int nf = 0; nf < 4; nf++)
                        mma16816(acc2[mf][nf], ah, bh[2 * nf], bh[2 * nf + 1]);
#pragma unroll
                    for (int nf = 0; nf < 4; nf++)
                        mma16816(acc2[mf][nf], ah, bl[2 * nf], bl[2 * nf + 1]);
#pragma unroll
                    for (int nf = 0; nf < 4; nf++)
                        mma16816(acc2[mf][nf], al, bh[2 * nf], bh[2 * nf + 1]);
                }
            }
        }

        // epilogue: partial stores (same mapping/values as before)
#pragma unroll
        for (int mf = 0; mf < 2; mf++)
#pragma unroll
            for (int hr = 0; hr < 2; hr++) {
                if (mrow[mf][hr] < cnt) {
                    float* yr = g_part + ((size_t)slotr[mf][hr] * NTOK + tokr[mf][hr]) * TOUT + n0;
#pragma unroll
                    for (int nf = 0; nf < 4; nf++) {
                        const int n = warp_n * 32 + nf * 8 + 2 * (lane & 3);
                        float2 v;
                        v.x = acc2[mf][nf][2 * hr + 0];
                        v.y = acc2[mf][nf][2 * hr + 1];
                        *(float2*)(yr + n) = v;
                    }
                }
            }
    }
}

// ---------------- kernel 5: finish — y = p0 + p1, EPS fixup; reset g_cnt ----------------
__global__ void finish_kernel(float4* __restrict__ y) {
    if (blockIdx.x == 0 && threadIdx.x < NEXP) g_cnt[threadIdx.x] = 0;  // clean for next launch
    const int n = NTOK * TOUT / 4;
    const float4* p0 = (const float4*)g_part;
    const float4* p1 = (const float4*)(g_part + (size_t)NTOK * TOUT);
    for (int i = blockIdx.x * blockDim.x + threadIdx.x; i < n;
         i += gridDim.x * blockDim.x) {
        const float4 a = p0[i];
        const float4 b = p1[i];
        float4 v;
        v.x = a.x + b.x; v.y = a.y + b.y; v.z = a.z + b.z; v.w = a.w + b.w;
        if (v.x == 0.f) v.x = EPSV;
        if (v.y == 0.f) v.y = EPSV;
        if (v.z == 0.f) v.z = EPSV;
        if (v.w == 0.f) v.w = EPSV;
        y[i] = v;
    }
}

// ---------------- launch ----------------
extern "C" void kernel_launch(void* const* d_in, const int* in_sizes, int n_in,
                              void* d_out, int out_size) {
    const float* x  = (const float*)d_in[0];
    // d_in[1] = labels (int64) — unused by the reference computation
    const float* wg = (const float*)d_in[2];
    const float* W1 = (const float*)d_in[3];
    const float* b1 = (const float*)d_in[4];
    const float* W2 = (const float*)d_in[5];
    const float* b2 = (const float*)d_in[6];
    const float* Wm = (const float*)d_in[7];
    float* y = (float*)d_out;

    cudaFuncSetAttribute(fc1_mma,    cudaFuncAttributeMaxDynamicSharedMemorySize, SMEM_FC1);
    cudaFuncSetAttribute(fc2cmb_mma, cudaFuncAttributeMaxDynamicSharedMemorySize, SMEM_F2C);

    prep_kernel<<<NTOK / 8 + 512, 256>>>(x, wg, W1, W2, Wm);

    dim3 g1(NTOK / 128, HDIM / 128, NEXP);  // (64, 2, 8)
    fc1_mma<<<g1, 256, SMEM_FC1>>>(b1);

    dim3 g2(NTOK / 64, 1, NEXP);            // (128, 1, 8)
    fc2cmb_mma<<<g2, 256, SMEM_F2C>>>(b2);

    finish_kernel<<<1024, 256>>>((float4*)y);
}